// round 14
// baseline (speedup 1.0000x reference)
#include <cuda_runtime.h>
#include <cuda_fp16.h>
#include <cstdint>
#include <math.h>

#define NMAX 100000
#define EMAX 500000
#define AWX 16384     // xgemm A tile: 256 rows x 128 k fp16 (64KB)
#define AWE 8192      // edge  A tile: 128 rows x 128 k fp16 (32KB)
#define BWORDS 4096   // B tile: 128 k x 64 n fp16 (16KB)

// ---------------- scratch ----------------------------------------------------
__device__ __align__(16) __half g_XAB[(size_t)NMAX * 768];   // [XA|XB] fp16
__device__ __align__(16) float g_H[(size_t)NMAX * 128];
__device__ __align__(16) unsigned g_Wp[20 * BWORDS];         // permuted fp16 weights
__device__ float g_signal[NMAX];
__device__ int   g_elist[EMAX];
__device__ int   g_ecount;
__device__ int   g_idx64;

// ---------------- helpers -----------------------------------------------------
__device__ __forceinline__ void mma16(float* c, uint4 a, unsigned b0, unsigned b1) {
    asm volatile(
        "mma.sync.aligned.m16n8k16.row.col.f32.f16.f16.f32 "
        "{%0,%1,%2,%3},{%4,%5,%6,%7},{%8,%9},{%0,%1,%2,%3};"
        : "+f"(c[0]), "+f"(c[1]), "+f"(c[2]), "+f"(c[3])
        : "r"(a.x), "r"(a.y), "r"(a.z), "r"(a.w), "r"(b0), "r"(b1));
}
__device__ __forceinline__ void cp16(void* sdst, const void* gsrc) {
    unsigned s = (unsigned)__cvta_generic_to_shared(sdst);
    asm volatile("cp.async.cg.shared.global [%0], [%1], 16;\n" :: "r"(s), "l"(gsrc));
}
__device__ __forceinline__ void cp_commit() { asm volatile("cp.async.commit_group;\n" ::); }
__device__ __forceinline__ void cp_wait0()  { asm volatile("cp.async.wait_group 0;\n" ::: "memory"); }
__device__ __forceinline__ void cp_wait1()  { asm volatile("cp.async.wait_group 1;\n" ::: "memory"); }
__device__ __forceinline__ unsigned h2b(float a, float b) {
    __half2 h = __floats2half2_rn(a, b);
    return *reinterpret_cast<unsigned*>(&h);
}

// A permuted word position, 256-row tile (xgemm)
__device__ __forceinline__ int aposx(int r, int k) {
    int wm = r >> 6, mi = (r >> 4) & 3, jbit = (r >> 3) & 1, g = r & 7;
    int kblk = k >> 4, khalf = (k >> 3) & 1, t4 = (k >> 1) & 3;
    return ((wm * 8 + kblk) * 4 + mi) * 128 + (g * 4 + t4) * 4 + khalf * 2 + jbit;
}
// A permuted word position, 128-row tile (edge)
__device__ __forceinline__ int apose(int r, int k) {
    int wm = r >> 5, mi = (r >> 4) & 1, jbit = (r >> 3) & 1, g = r & 7;
    int kblk = k >> 4, khalf = (k >> 3) & 1, t4 = (k >> 1) & 3;
    return ((wm * 8 + kblk) * 2 + mi) * 128 + (g * 4 + t4) * 4 + khalf * 2 + jbit;
}

// ---------------- prep: permute+convert weights to fp16 ----------------------
// tiles: 0..5 V1[0:128], 6..11 V1[128:256], 12..13 W1, 14..19 V1[256:384]
__global__ void prep_kernel(const float* __restrict__ V1, const float* __restrict__ W1) {
    int idx = blockIdx.x * blockDim.x + threadIdx.x;
    if (idx >= 20 * BWORDS) return;
    int tile = idx >> 12;
    int rem  = idx & 4095;
    int kblk = rem >> 9;
    int wn   = (rem >> 8) & 1;
    int h    = (rem >> 7) & 1;
    int lane = (rem >> 2) & 31;
    int nlow = (rem >> 1) & 1;
    int khalf = rem & 1;
    int g = lane >> 2, t4 = lane & 3;
    int ni = 2 * h + nlow;
    int n  = wn * 32 + ni * 8 + g;
    int k  = kblk * 16 + khalf * 8 + t4 * 2;
    float va, vb;
    if (tile < 6) {
        va = V1[(size_t)k * 384 + tile * 64 + n];
        vb = V1[(size_t)(k + 1) * 384 + tile * 64 + n];
    } else if (tile < 12) {
        va = V1[(size_t)(128 + k) * 384 + (tile - 6) * 64 + n];
        vb = V1[(size_t)(129 + k) * 384 + (tile - 6) * 64 + n];
    } else if (tile < 14) {
        va = W1[(size_t)k * 128 + (tile - 12) * 64 + n];
        vb = W1[(size_t)(k + 1) * 128 + (tile - 12) * 64 + n];
    } else {
        va = V1[(size_t)(256 + k) * 384 + (tile - 14) * 64 + n];
        vb = V1[(size_t)(257 + k) * 384 + (tile - 14) * 64 + n];
    }
    g_Wp[idx] = h2b(va, vb);
}

// ---------------- init / compact ---------------------------------------------
__global__ void init_kernel(int N, const int* __restrict__ ei_raw) {
    int i = blockIdx.x * blockDim.x + threadIdx.x;
    if (i == 0) {
        g_ecount = 0;
        int allz = 1;
        #pragma unroll
        for (int j = 1; j < 64; j += 2)
            if (ei_raw[j] != 0) { allz = 0; break; }
        g_idx64 = allz;
    }
    if (i < N) g_signal[i] = 0.0f;
}

__global__ void compact_kernel(const int* __restrict__ ei, int E,
                               const int* __restrict__ bs_ptr) {
    __shared__ int s_cnt, s_base;
    int e = blockIdx.x * blockDim.x + threadIdx.x;
    if (threadIdx.x == 0) s_cnt = 0;
    __syncthreads();
    int pos = -1;
    if (e < E) {
        int bs  = *bs_ptr;
        int src = g_idx64 ? ei[2 * e] : ei[e];
        if (src < bs) pos = atomicAdd(&s_cnt, 1);
    }
    __syncthreads();
    if (threadIdx.x == 0 && s_cnt > 0) s_base = atomicAdd(&g_ecount, s_cnt);
    __syncthreads();
    if (pos >= 0) g_elist[s_base + pos] = e;
}

// ---------------- fused x-GEMM: persistent A (256 rows), loop ct tiles -------
__global__ __launch_bounds__(256, 2) void xgemm_mma(
    const float* __restrict__ x, const float* __restrict__ b1,
    int N, const int* __restrict__ bs_ptr)
{
    extern __shared__ unsigned usm[];
    unsigned* As  = usm;                 // AWX (persistent)
    unsigned* Bb0 = usm + AWX;           // BWORDS each
    unsigned* Bb1 = Bb0 + BWORDS;

    int bs = *bs_ptr; if (bs > N) bs = N;
    int row0 = blockIdx.x * 256;
    if (row0 >= N) return;
    int ne = min(256, N - row0);
    int t = threadIdx.x;

    int tbase  = (row0 < bs) ? 0 : 6;
    int ntiles = (row0 < bs) ? 14 : 6;

    for (int i = t; i < BWORDS / 4; i += 256)
        cp16(&Bb0[i * 4], &g_Wp[tbase * BWORDS + i * 4]);
    cp_commit();

    for (int i = t; i < 4096; i += 256) {
        int r = i >> 4, c = i & 15;
        int rs = (r < ne) ? (row0 + r) : row0;
        const float4* xp = (const float4*)(x + (size_t)rs * 128 + c * 8);
        float4 v0 = xp[0], v1 = xp[1];
        int k0 = c * 8;
        As[aposx(r, k0)]     = h2b(v0.x, v0.y);
        As[aposx(r, k0 + 2)] = h2b(v0.z, v0.w);
        As[aposx(r, k0 + 4)] = h2b(v1.x, v1.y);
        As[aposx(r, k0 + 6)] = h2b(v1.z, v1.w);
    }

    int lane = t & 31, w = t >> 5;
    int wm = w >> 1, wn = w & 1;         // 4 x 2 warps, warp tile 64x32
    int g = lane >> 2, t4 = lane & 3;

    const uint4* Au = (const uint4*)As;

    #pragma unroll 1
    for (int ti = 0; ti < ntiles; ++ti) {
        int ct = tbase + ti;
        const uint4* Bu = (const uint4*)((ti & 1) ? Bb1 : Bb0);
        unsigned* Bn = (ti & 1) ? Bb0 : Bb1;

        __syncthreads();
        if (ti + 1 < ntiles) {
            for (int i = t; i < BWORDS / 4; i += 256)
                cp16(&Bn[i * 4], &g_Wp[(ct + 1) * BWORDS + i * 4]);
        }
        cp_commit();
        cp_wait1();
        __syncthreads();

        float C[4][4][4] = {};
        #pragma unroll
        for (int kb = 0; kb < 8; kb++) {
            uint4 a0 = Au[((wm * 8 + kb) * 4 + 0) * 32 + lane];
            uint4 a1 = Au[((wm * 8 + kb) * 4 + 1) * 32 + lane];
            uint4 a2 = Au[((wm * 8 + kb) * 4 + 2) * 32 + lane];
            uint4 a3 = Au[((wm * 8 + kb) * 4 + 3) * 32 + lane];
            uint4 b0 = Bu[((kb * 2 + wn) * 2 + 0) * 32 + lane];
            uint4 b1 = Bu[((kb * 2 + wn) * 2 + 1) * 32 + lane];
            mma16(C[0][0], a0, b0.x, b0.y);  mma16(C[0][1], a0, b0.z, b0.w);
            mma16(C[0][2], a0, b1.x, b1.y);  mma16(C[0][3], a0, b1.z, b1.w);
            mma16(C[1][0], a1, b0.x, b0.y);  mma16(C[1][1], a1, b0.z, b0.w);
            mma16(C[1][2], a1, b1.x, b1.y);  mma16(C[1][3], a1, b1.z, b1.w);
            mma16(C[2][0], a2, b0.x, b0.y);  mma16(C[2][1], a2, b0.z, b0.w);
            mma16(C[2][2], a2, b1.x, b1.y);  mma16(C[2][3], a2, b1.z, b1.w);
            mma16(C[3][0], a3, b0.x, b0.y);  mma16(C[3][1], a3, b0.z, b0.w);
            mma16(C[3][2], a3, b1.x, b1.y);  mma16(C[3][3], a3, b1.z, b1.w);
        }

        bool isH = (ct >= 12);
        int mlim = (ct >= 6 && ct < 12) ? ne : min(ne, bs - row0);
        #pragma unroll
        for (int mi = 0; mi < 4; mi++)
            #pragma unroll
            for (int ni = 0; ni < 4; ni++) {
                int ncl = wn * 32 + ni * 8 + 2 * t4;
                #pragma unroll
                for (int half = 0; half < 2; half++) {
                    int r = wm * 64 + mi * 16 + g + half * 8;
                    if (r < mlim) {
                        float v0 = C[mi][ni][half * 2 + 0];
                        float v1 = C[mi][ni][half * 2 + 1];
                        size_t row = row0 + r;
                        if (isH) {
                            int jg = (ct - 12) * 64 + ncl;
                            float2 o;
                            o.x = fmaxf(v0 + b1[jg],     0.f);
                            o.y = fmaxf(v1 + b1[jg + 1], 0.f);
                            *(float2*)(g_H + row * 128 + jg) = o;
                        } else {
                            int jg = ct * 64 + ncl;
                            __half2 o = __floats2half2_rn(v0, v1);
                            *reinterpret_cast<__half2*>(g_XAB + row * 768 + jg) = o;
                        }
                    }
                }
            }
    }
}

// ---------------- edge kernel: 128 edges/block, ALL 6 B tiles resident -------
__global__ __launch_bounds__(256, 1) void edge_mma(
    const float* __restrict__ edge_attr,
    const float* __restrict__ bv1, const float* __restrict__ V2,
    const float* __restrict__ bv2, const int* __restrict__ ei, int E)
{
    extern __shared__ unsigned usm[];
    unsigned* As   = usm;            // AWE
    unsigned* Bres = usm + AWE;      // 6 * BWORDS (96KB) resident

    __shared__ int s_src[128], s_dst[128], s_eid[128];
    __shared__ float s_part[128 * 2];

    int cnt = g_ecount;
    int base = blockIdx.x * 128;
    if (base >= cnt) return;
    int ne = min(128, cnt - base);
    int t = threadIdx.x;
    int i64 = g_idx64;

    if (t < 128) {
        int e = 0, ss = 0, dd = 0;
        if (t < ne) {
            e  = g_elist[base + t];
            ss = i64 ? ei[2 * e]       : ei[e];
            dd = i64 ? ei[2 * (E + e)] : ei[E + e];
        }
        s_eid[t] = e; s_src[t] = ss; s_dst[t] = dd;
    }
    s_part[t] = 0.f;
    __syncthreads();

    // load ALL 6 B tiles (weights 14..19, contiguous in g_Wp) in one burst
    for (int i = t; i < 6 * BWORDS / 4; i += 256)
        cp16(&Bres[i * 4], &g_Wp[14 * BWORDS + i * 4]);
    cp_commit();

    // As: gather + convert + permute
    for (int i = t; i < 2048; i += 256) {
        int r = i >> 4, c = i & 15;
        const float4* xp = (const float4*)(edge_attr + (size_t)s_eid[r] * 128 + c * 8);
        float4 v0 = xp[0], v1 = xp[1];
        int k0 = c * 8;
        As[apose(r, k0)]     = h2b(v0.x, v0.y);
        As[apose(r, k0 + 2)] = h2b(v0.z, v0.w);
        As[apose(r, k0 + 4)] = h2b(v1.x, v1.y);
        As[apose(r, k0 + 6)] = h2b(v1.z, v1.w);
    }
    cp_wait0();
    __syncthreads();          // ONE barrier; no more until the final reduction

    int lane = t & 31, w = t >> 5;
    int wm = w >> 1, wn = w & 1;      // 4 x 2 warps, warp tile 32x32
    int g = lane >> 2, t4 = lane & 3;
    float psc[2][2] = {};

    const uint4* Au = (const uint4*)As;

    #pragma unroll 1
    for (int ct = 0; ct < 6; ++ct) {
        const uint4* Bu = (const uint4*)(Bres + ct * BWORDS);

        // prefetch fp16 XA/XB epilogue values for this ct
        unsigned pxa[2][2][4], pxb[2][2][4];
        #pragma unroll
        for (int mi = 0; mi < 2; mi++)
            #pragma unroll
            for (int half = 0; half < 2; half++) {
                int r = wm * 32 + mi * 16 + g + half * 8;
                const __half* pa = g_XAB + (size_t)s_src[r] * 768 + ct * 64;
                const __half* pb = g_XAB + (size_t)s_dst[r] * 768 + 384 + ct * 64;
                #pragma unroll
                for (int ni = 0; ni < 4; ni++) {
                    int ncl = wn * 32 + ni * 8 + 2 * t4;
                    pxa[mi][half][ni] = *reinterpret_cast<const unsigned*>(pa + ncl);
                    pxb[mi][half][ni] = *reinterpret_cast<const unsigned*>(pb + ncl);
                }
            }

        float C[2][4][4] = {};
        #pragma unroll
        for (int kb = 0; kb < 8; kb++) {
            uint4 a0 = Au[((wm * 8 + kb) * 2 + 0) * 32 + lane];
            uint4 a1 = Au[((wm * 8 + kb) * 2 + 1) * 32 + lane];
            uint4 b0 = Bu[((kb * 2 + wn) * 2 + 0) * 32 + lane];
            uint4 b1 = Bu[((kb * 2 + wn) * 2 + 1) * 32 + lane];
            mma16(C[0][0], a0, b0.x, b0.y);
            mma16(C[0][1], a0, b0.z, b0.w);
            mma16(C[0][2], a0, b1.x, b1.y);
            mma16(C[0][3], a0, b1.z, b1.w);
            mma16(C[1][0], a1, b0.x, b0.y);
            mma16(C[1][1], a1, b0.z, b0.w);
            mma16(C[1][2], a1, b1.x, b1.y);
            mma16(C[1][3], a1, b1.z, b1.w);
        }

        #pragma unroll
        for (int mi = 0; mi < 2; mi++)
            #pragma unroll
            for (int half = 0; half < 2; half++) {
                int r = wm * 32 + mi * 16 + g + half * 8;
                if (r < ne) {
                    #pragma unroll
                    for (int ni = 0; ni < 4; ni++) {
                        int ncl = wn * 32 + ni * 8 + 2 * t4;
                        int jg  = ct * 64 + ncl;
                        float2 bv = *(const float2*)(bv1 + jg);
                        float2 v2 = *(const float2*)(V2 + jg);
                        float2 fa = __half22float2(
                            *reinterpret_cast<__half2*>(&pxa[mi][half][ni]));
                        float2 fb = __half22float2(
                            *reinterpret_cast<__half2*>(&pxb[mi][half][ni]));
                        float h0 = fmaxf(C[mi][ni][half * 2 + 0] + fa.x + fb.x + bv.x, 0.f);
                        float h1 = fmaxf(C[mi][ni][half * 2 + 1] + fa.y + fb.y + bv.y, 0.f);
                        psc[mi][half] += h0 * v2.x + h1 * v2.y;
                    }
                }
            }
    }

    // deterministic per-edge reduction
    #pragma unroll
    for (int mi = 0; mi < 2; mi++)
        #pragma unroll
        for (int half = 0; half < 2; half++) {
            float v = psc[mi][half];
            v += __shfl_xor_sync(0xffffffffu, v, 1);
            v += __shfl_xor_sync(0xffffffffu, v, 2);
            int r = wm * 32 + mi * 16 + g + half * 8;
            if (t4 == 0 && r < ne) s_part[r * 2 + wn] = v;
        }
    __syncthreads();

    if (t < ne) {
        float score = (s_part[t * 2 + 0] + s_part[t * 2 + 1]) + bv2[0];
        float sig = 1.0f / (1.0f + expf(-score));
        atomicMax((int*)&g_signal[s_src[t]], __float_as_int(sig));
    }
}

// ---------------- final: pred = H@W2 + b2 (+signal), labels ------------------
__global__ __launch_bounds__(256) void final_kernel(
    const float* __restrict__ W2, const float* __restrict__ b2,
    const float* __restrict__ ecw, const int* __restrict__ y,
    const int* __restrict__ bs_ptr, float* __restrict__ out,
    int out_size, int N)
{
    int bs = *bs_ptr; if (bs > N) bs = N;
    int row  = (blockIdx.x * blockDim.x + threadIdx.x) >> 5;
    int lane = threadIdx.x & 31;
    if (row >= bs) return;

    float4 hv  = *(const float4*)(g_H + (size_t)row * 128 + lane * 4);
    float4 w01 = *(const float4*)(W2 + lane * 8);
    float4 w23 = *(const float4*)(W2 + lane * 8 + 4);
    float d0 = hv.x * w01.x + hv.y * w01.z + hv.z * w23.x + hv.w * w23.z;
    float d1 = hv.x * w01.y + hv.y * w01.w + hv.z * w23.y + hv.w * w23.w;
    #pragma unroll
    for (int off = 16; off >= 1; off >>= 1) {
        d0 += __shfl_xor_sync(0xffffffffu, d0, off);
        d1 += __shfl_xor_sync(0xffffffffu, d1, off);
    }
    if (lane == 0) {
        out[(size_t)row * 2 + 0] = d0 + b2[0];
        out[(size_t)row * 2 + 1] = d1 + b2[1] + (*ecw) * g_signal[row];
        if (out_size >= 3 * bs) {
            int lab = g_idx64 ? y[2 * row] : y[row];
            out[(size_t)2 * bs + row] = (float)lab;
        }
    }
}

// ---------------- launch -----------------------------------------------------
extern "C" void kernel_launch(void* const* d_in, const int* in_sizes, int n_in,
                              void* d_out, int out_size) {
    const float* x         = (const float*)d_in[0];
    const float* edge_attr = (const float*)d_in[1];
    const float* W1        = (const float*)d_in[2];
    const float* b1        = (const float*)d_in[3];
    const float* W2        = (const float*)d_in[4];
    const float* b2        = (const float*)d_in[5];
    const float* V1        = (const float*)d_in[6];
    const float* bv1       = (const float*)d_in[7];
    const float* V2        = (const float*)d_in[8];
    const float* bv2       = (const float*)d_in[9];
    const float* ecw       = (const float*)d_in[10];
    const int*   ei        = (const int*)d_in[11];
    const int*   y         = (const int*)d_in[12];
    const int*   bs_ptr    = (const int*)d_in[13];
    float* out = (float*)d_out;

    int N = in_sizes[0] / 128;
    int E = in_sizes[1] / 128;

    int xg_smem = (AWX + 2 * BWORDS) * 4;   // 96 KB
    int eg_smem = (AWE + 6 * BWORDS) * 4;   // 128 KB
    cudaFuncSetAttribute(xgemm_mma, cudaFuncAttributeMaxDynamicSharedMemorySize, xg_smem);
    cudaFuncSetAttribute(edge_mma,  cudaFuncAttributeMaxDynamicSharedMemorySize, eg_smem);

    prep_kernel<<<(20 * BWORDS + 255) / 256, 256>>>(V1, W1);
    init_kernel<<<(N + 255) / 256, 256>>>(N, ei);
    compact_kernel<<<(E + 255) / 256, 256>>>(ei, E, bs_ptr);

    xgemm_mma<<<(N + 255) / 256, 256, xg_smem>>>(x, b1, N, bs_ptr);

    edge_mma<<<(E + 127) / 128, 256, eg_smem>>>(edge_attr, bv1, V2, bv2, ei, E);

    final_kernel<<<(N * 32 + 255) / 256, 256>>>(W2, b2, ecw, y, bs_ptr, out, out_size, N);
}

// round 16
// speedup vs baseline: 1.1245x; 1.1245x over previous
#include <cuda_runtime.h>
#include <cuda_fp16.h>
#include <cstdint>
#include <math.h>

#define NMAX 100000
#define EMAX 500000
#define AWX 16384     // xgemm A tile: 256 rows x 128 k fp16 (64KB)
#define AWE 8192      // edge  A tile: 128 rows x 128 k fp16 (32KB)
#define BWORDS 4096   // B tile: 128 k x 64 n fp16 (16KB)

// ---------------- scratch ----------------------------------------------------
__device__ __align__(16) __half g_XAB[(size_t)NMAX * 768];   // [XA|XB] fp16
__device__ __align__(16) float g_H[(size_t)NMAX * 128];
__device__ __align__(16) unsigned g_Wp[20 * BWORDS];         // permuted fp16 weights
__device__ float g_signal[NMAX];
__device__ int   g_elist[EMAX];
__device__ int   g_ecount;
__device__ int   g_idx64;

// ---------------- helpers -----------------------------------------------------
__device__ __forceinline__ void mma16(float* c, uint4 a, unsigned b0, unsigned b1) {
    asm volatile(
        "mma.sync.aligned.m16n8k16.row.col.f32.f16.f16.f32 "
        "{%0,%1,%2,%3},{%4,%5,%6,%7},{%8,%9},{%0,%1,%2,%3};"
        : "+f"(c[0]), "+f"(c[1]), "+f"(c[2]), "+f"(c[3])
        : "r"(a.x), "r"(a.y), "r"(a.z), "r"(a.w), "r"(b0), "r"(b1));
}
__device__ __forceinline__ void cp16(void* sdst, const void* gsrc) {
    unsigned s = (unsigned)__cvta_generic_to_shared(sdst);
    asm volatile("cp.async.cg.shared.global [%0], [%1], 16;\n" :: "r"(s), "l"(gsrc));
}
__device__ __forceinline__ void cp_commit() { asm volatile("cp.async.commit_group;\n" ::); }
__device__ __forceinline__ void cp_wait1()  { asm volatile("cp.async.wait_group 1;\n" ::: "memory"); }
__device__ __forceinline__ unsigned h2b(float a, float b) {
    __half2 h = __floats2half2_rn(a, b);
    return *reinterpret_cast<unsigned*>(&h);
}

// A permuted word position, 256-row tile (xgemm)
__device__ __forceinline__ int aposx(int r, int k) {
    int wm = r >> 6, mi = (r >> 4) & 3, jbit = (r >> 3) & 1, g = r & 7;
    int kblk = k >> 4, khalf = (k >> 3) & 1, t4 = (k >> 1) & 3;
    return ((wm * 8 + kblk) * 4 + mi) * 128 + (g * 4 + t4) * 4 + khalf * 2 + jbit;
}
// A permuted word position, 128-row tile (edge)
__device__ __forceinline__ int apose(int r, int k) {
    int wm = r >> 5, mi = (r >> 4) & 1, jbit = (r >> 3) & 1, g = r & 7;
    int kblk = k >> 4, khalf = (k >> 3) & 1, t4 = (k >> 1) & 3;
    return ((wm * 8 + kblk) * 2 + mi) * 128 + (g * 4 + t4) * 4 + khalf * 2 + jbit;
}

// ---------------- prep: permute+convert weights to fp16 ----------------------
// tiles: 0..5 V1[0:128], 6..11 V1[128:256], 12..13 W1, 14..19 V1[256:384]
__global__ void prep_kernel(const float* __restrict__ V1, const float* __restrict__ W1) {
    int idx = blockIdx.x * blockDim.x + threadIdx.x;
    if (idx == 0) g_ecount = 0;          // zero before init_compact (stream-ordered)
    if (idx >= 20 * BWORDS) return;
    int tile = idx >> 12;
    int rem  = idx & 4095;
    int kblk = rem >> 9;
    int wn   = (rem >> 8) & 1;
    int h    = (rem >> 7) & 1;
    int lane = (rem >> 2) & 31;
    int nlow = (rem >> 1) & 1;
    int khalf = rem & 1;
    int g = lane >> 2, t4 = lane & 3;
    int ni = 2 * h + nlow;
    int n  = wn * 32 + ni * 8 + g;
    int k  = kblk * 16 + khalf * 8 + t4 * 2;
    float va, vb;
    if (tile < 6) {
        va = V1[(size_t)k * 384 + tile * 64 + n];
        vb = V1[(size_t)(k + 1) * 384 + tile * 64 + n];
    } else if (tile < 12) {
        va = V1[(size_t)(128 + k) * 384 + (tile - 6) * 64 + n];
        vb = V1[(size_t)(129 + k) * 384 + (tile - 6) * 64 + n];
    } else if (tile < 14) {
        va = W1[(size_t)k * 128 + (tile - 12) * 64 + n];
        vb = W1[(size_t)(k + 1) * 128 + (tile - 12) * 64 + n];
    } else {
        va = V1[(size_t)(256 + k) * 384 + (tile - 14) * 64 + n];
        vb = V1[(size_t)(257 + k) * 384 + (tile - 14) * 64 + n];
    }
    g_Wp[idx] = h2b(va, vb);
}

// ---------------- fused init + compact (per-block idx64 sniff) ---------------
__global__ void init_compact_kernel(const int* __restrict__ ei, int E, int N,
                                    const int* __restrict__ bs_ptr) {
    __shared__ int s_cnt, s_base, s_i64;
    int t = threadIdx.x;
    int e = blockIdx.x * blockDim.x + t;
    if (t == 0) {
        s_cnt = 0;
        int allz = 1;
        #pragma unroll
        for (int j = 1; j < 64; j += 2)
            if (ei[j] != 0) { allz = 0; break; }
        s_i64 = allz;
        if (blockIdx.x == 0) g_idx64 = allz;
    }
    __syncthreads();
    if (e < N) g_signal[e] = 0.0f;
    int pos = -1;
    if (e < E) {
        int bs  = *bs_ptr;
        int src = s_i64 ? ei[2 * e] : ei[e];
        if (src < bs) pos = atomicAdd(&s_cnt, 1);
    }
    __syncthreads();
    if (t == 0 && s_cnt > 0) s_base = atomicAdd(&g_ecount, s_cnt);
    __syncthreads();
    if (pos >= 0) g_elist[s_base + pos] = e;
}

// ---------------- fused x-GEMM: persistent A (256 rows), loop ct tiles -------
__global__ __launch_bounds__(256, 2) void xgemm_mma(
    const float* __restrict__ x, const float* __restrict__ b1,
    int N, const int* __restrict__ bs_ptr)
{
    extern __shared__ unsigned usm[];
    unsigned* As  = usm;                 // AWX (persistent)
    unsigned* Bb0 = usm + AWX;           // BWORDS each
    unsigned* Bb1 = Bb0 + BWORDS;

    int bs = *bs_ptr; if (bs > N) bs = N;
    int row0 = blockIdx.x * 256;
    if (row0 >= N) return;
    int ne = min(256, N - row0);
    int t = threadIdx.x;

    int tbase  = (row0 < bs) ? 0 : 6;
    int ntiles = (row0 < bs) ? 14 : 6;

    for (int i = t; i < BWORDS / 4; i += 256)
        cp16(&Bb0[i * 4], &g_Wp[tbase * BWORDS + i * 4]);
    cp_commit();

    for (int i = t; i < 4096; i += 256) {
        int r = i >> 4, c = i & 15;
        int rs = (r < ne) ? (row0 + r) : row0;
        const float4* xp = (const float4*)(x + (size_t)rs * 128 + c * 8);
        float4 v0 = xp[0], v1 = xp[1];
        int k0 = c * 8;
        As[aposx(r, k0)]     = h2b(v0.x, v0.y);
        As[aposx(r, k0 + 2)] = h2b(v0.z, v0.w);
        As[aposx(r, k0 + 4)] = h2b(v1.x, v1.y);
        As[aposx(r, k0 + 6)] = h2b(v1.z, v1.w);
    }

    int lane = t & 31, w = t >> 5;
    int wm = w >> 1, wn = w & 1;         // 4 x 2 warps, warp tile 64x32
    int g = lane >> 2, t4 = lane & 3;

    const uint4* Au = (const uint4*)As;

    #pragma unroll 1
    for (int ti = 0; ti < ntiles; ++ti) {
        int ct = tbase + ti;
        const uint4* Bu = (const uint4*)((ti & 1) ? Bb1 : Bb0);
        unsigned* Bn = (ti & 1) ? Bb0 : Bb1;

        __syncthreads();
        if (ti + 1 < ntiles) {
            for (int i = t; i < BWORDS / 4; i += 256)
                cp16(&Bn[i * 4], &g_Wp[(ct + 1) * BWORDS + i * 4]);
        }
        cp_commit();
        cp_wait1();
        __syncthreads();

        float C[4][4][4] = {};
        #pragma unroll
        for (int kb = 0; kb < 8; kb++) {
            uint4 a0 = Au[((wm * 8 + kb) * 4 + 0) * 32 + lane];
            uint4 a1 = Au[((wm * 8 + kb) * 4 + 1) * 32 + lane];
            uint4 a2 = Au[((wm * 8 + kb) * 4 + 2) * 32 + lane];
            uint4 a3 = Au[((wm * 8 + kb) * 4 + 3) * 32 + lane];
            uint4 b0 = Bu[((kb * 2 + wn) * 2 + 0) * 32 + lane];
            uint4 b1 = Bu[((kb * 2 + wn) * 2 + 1) * 32 + lane];
            mma16(C[0][0], a0, b0.x, b0.y);  mma16(C[0][1], a0, b0.z, b0.w);
            mma16(C[0][2], a0, b1.x, b1.y);  mma16(C[0][3], a0, b1.z, b1.w);
            mma16(C[1][0], a1, b0.x, b0.y);  mma16(C[1][1], a1, b0.z, b0.w);
            mma16(C[1][2], a1, b1.x, b1.y);  mma16(C[1][3], a1, b1.z, b1.w);
            mma16(C[2][0], a2, b0.x, b0.y);  mma16(C[2][1], a2, b0.z, b0.w);
            mma16(C[2][2], a2, b1.x, b1.y);  mma16(C[2][3], a2, b1.z, b1.w);
            mma16(C[3][0], a3, b0.x, b0.y);  mma16(C[3][1], a3, b0.z, b0.w);
            mma16(C[3][2], a3, b1.x, b1.y);  mma16(C[3][3], a3, b1.z, b1.w);
        }

        bool isH = (ct >= 12);
        int mlim = (ct >= 6 && ct < 12) ? ne : min(ne, bs - row0);
        #pragma unroll
        for (int mi = 0; mi < 4; mi++)
            #pragma unroll
            for (int ni = 0; ni < 4; ni++) {
                int ncl = wn * 32 + ni * 8 + 2 * t4;
                #pragma unroll
                for (int half = 0; half < 2; half++) {
                    int r = wm * 64 + mi * 16 + g + half * 8;
                    if (r < mlim) {
                        float v0 = C[mi][ni][half * 2 + 0];
                        float v1 = C[mi][ni][half * 2 + 1];
                        size_t row = row0 + r;
                        if (isH) {
                            int jg = (ct - 12) * 64 + ncl;
                            float2 o;
                            o.x = fmaxf(v0 + b1[jg],     0.f);
                            o.y = fmaxf(v1 + b1[jg + 1], 0.f);
                            *(float2*)(g_H + row * 128 + jg) = o;
                        } else {
                            int jg = ct * 64 + ncl;
                            __half2 o = __floats2half2_rn(v0, v1);
                            *reinterpret_cast<__half2*>(g_XAB + row * 768 + jg) = o;
                        }
                    }
                }
            }
    }
}

// ---------------- edge kernel: 128 edges/block, double-buffered B ------------
__global__ __launch_bounds__(256, 2) void edge_mma(
    const float* __restrict__ edge_attr,
    const float* __restrict__ bv1, const float* __restrict__ V2,
    const float* __restrict__ bv2, const int* __restrict__ ei, int E)
{
    extern __shared__ unsigned usm[];
    unsigned* As  = usm;
    unsigned* Bb0 = usm + AWE;
    unsigned* Bb1 = Bb0 + BWORDS;

    __shared__ int s_src[128], s_dst[128], s_eid[128];
    __shared__ float s_part[128 * 2];

    int cnt = g_ecount;
    int base = blockIdx.x * 128;
    if (base >= cnt) return;
    int ne = min(128, cnt - base);
    int t = threadIdx.x;
    int i64 = g_idx64;

    if (t < 128) {
        int e = 0, ss = 0, dd = 0;
        if (t < ne) {
            e  = g_elist[base + t];
            ss = i64 ? ei[2 * e]       : ei[e];
            dd = i64 ? ei[2 * (E + e)] : ei[E + e];
        }
        s_eid[t] = e; s_src[t] = ss; s_dst[t] = dd;
    }
    s_part[t] = 0.f;
    __syncthreads();

    for (int i = t; i < BWORDS / 4; i += 256)
        cp16(&Bb0[i * 4], &g_Wp[14 * BWORDS + i * 4]);
    cp_commit();

    for (int i = t; i < 2048; i += 256) {
        int r = i >> 4, c = i & 15;
        const float4* xp = (const float4*)(edge_attr + (size_t)s_eid[r] * 128 + c * 8);
        float4 v0 = xp[0], v1 = xp[1];
        int k0 = c * 8;
        As[apose(r, k0)]     = h2b(v0.x, v0.y);
        As[apose(r, k0 + 2)] = h2b(v0.z, v0.w);
        As[apose(r, k0 + 4)] = h2b(v1.x, v1.y);
        As[apose(r, k0 + 6)] = h2b(v1.z, v1.w);
    }

    int lane = t & 31, w = t >> 5;
    int wm = w >> 1, wn = w & 1;      // 4 x 2 warps, warp tile 32x32
    int g = lane >> 2, t4 = lane & 3;
    float psc[2][2] = {};

    const uint4* Au = (const uint4*)As;

    #pragma unroll 1
    for (int ct = 0; ct < 6; ++ct) {
        const uint4* Bu = (const uint4*)((ct & 1) ? Bb1 : Bb0);
        unsigned* Bn = (ct & 1) ? Bb0 : Bb1;

        __syncthreads();
        if (ct < 5) {
            for (int i = t; i < BWORDS / 4; i += 256)
                cp16(&Bn[i * 4], &g_Wp[(15 + ct) * BWORDS + i * 4]);
        }
        cp_commit();

        // prefetch fp16 XA/XB epilogue values (overlaps the pipeline wait below)
        unsigned pxa[2][2][4], pxb[2][2][4];
        #pragma unroll
        for (int mi = 0; mi < 2; mi++)
            #pragma unroll
            for (int half = 0; half < 2; half++) {
                int r = wm * 32 + mi * 16 + g + half * 8;
                const __half* pa = g_XAB + (size_t)s_src[r] * 768 + ct * 64;
                const __half* pb = g_XAB + (size_t)s_dst[r] * 768 + 384 + ct * 64;
                #pragma unroll
                for (int ni = 0; ni < 4; ni++) {
                    int ncl = wn * 32 + ni * 8 + 2 * t4;
                    pxa[mi][half][ni] = *reinterpret_cast<const unsigned*>(pa + ncl);
                    pxb[mi][half][ni] = *reinterpret_cast<const unsigned*>(pb + ncl);
                }
            }

        cp_wait1();
        __syncthreads();

        float C[2][4][4] = {};
        #pragma unroll
        for (int kb = 0; kb < 8; kb++) {
            uint4 a0 = Au[((wm * 8 + kb) * 2 + 0) * 32 + lane];
            uint4 a1 = Au[((wm * 8 + kb) * 2 + 1) * 32 + lane];
            uint4 b0 = Bu[((kb * 2 + wn) * 2 + 0) * 32 + lane];
            uint4 b1 = Bu[((kb * 2 + wn) * 2 + 1) * 32 + lane];
            mma16(C[0][0], a0, b0.x, b0.y);
            mma16(C[0][1], a0, b0.z, b0.w);
            mma16(C[0][2], a0, b1.x, b1.y);
            mma16(C[0][3], a0, b1.z, b1.w);
            mma16(C[1][0], a1, b0.x, b0.y);
            mma16(C[1][1], a1, b0.z, b0.w);
            mma16(C[1][2], a1, b1.x, b1.y);
            mma16(C[1][3], a1, b1.z, b1.w);
        }

        #pragma unroll
        for (int mi = 0; mi < 2; mi++)
            #pragma unroll
            for (int half = 0; half < 2; half++) {
                int r = wm * 32 + mi * 16 + g + half * 8;
                if (r < ne) {
                    #pragma unroll
                    for (int ni = 0; ni < 4; ni++) {
                        int ncl = wn * 32 + ni * 8 + 2 * t4;
                        int jg  = ct * 64 + ncl;
                        float2 bv = *(const float2*)(bv1 + jg);
                        float2 v2 = *(const float2*)(V2 + jg);
                        float2 fa = __half22float2(
                            *reinterpret_cast<__half2*>(&pxa[mi][half][ni]));
                        float2 fb = __half22float2(
                            *reinterpret_cast<__half2*>(&pxb[mi][half][ni]));
                        float h0 = fmaxf(C[mi][ni][half * 2 + 0] + fa.x + fb.x + bv.x, 0.f);
                        float h1 = fmaxf(C[mi][ni][half * 2 + 1] + fa.y + fb.y + bv.y, 0.f);
                        psc[mi][half] += h0 * v2.x + h1 * v2.y;
                    }
                }
            }
    }

    // deterministic per-edge reduction
    #pragma unroll
    for (int mi = 0; mi < 2; mi++)
        #pragma unroll
        for (int half = 0; half < 2; half++) {
            float v = psc[mi][half];
            v += __shfl_xor_sync(0xffffffffu, v, 1);
            v += __shfl_xor_sync(0xffffffffu, v, 2);
            int r = wm * 32 + mi * 16 + g + half * 8;
            if (t4 == 0 && r < ne) s_part[r * 2 + wn] = v;
        }
    __syncthreads();

    if (t < ne) {
        float score = (s_part[t * 2 + 0] + s_part[t * 2 + 1]) + bv2[0];
        float sig = 1.0f / (1.0f + expf(-score));
        atomicMax((int*)&g_signal[s_src[t]], __float_as_int(sig));
    }
}

// ---------------- final: pred = H@W2 + b2 (+signal), labels ------------------
__global__ __launch_bounds__(256) void final_kernel(
    const float* __restrict__ W2, const float* __restrict__ b2,
    const float* __restrict__ ecw, const int* __restrict__ y,
    const int* __restrict__ bs_ptr, float* __restrict__ out,
    int out_size, int N)
{
    int bs = *bs_ptr; if (bs > N) bs = N;
    int row  = (blockIdx.x * blockDim.x + threadIdx.x) >> 5;
    int lane = threadIdx.x & 31;
    if (row >= bs) return;

    float4 hv  = *(const float4*)(g_H + (size_t)row * 128 + lane * 4);
    float4 w01 = *(const float4*)(W2 + lane * 8);
    float4 w23 = *(const float4*)(W2 + lane * 8 + 4);
    float d0 = hv.x * w01.x + hv.y * w01.z + hv.z * w23.x + hv.w * w23.z;
    float d1 = hv.x * w01.y + hv.y * w01.w + hv.z * w23.y + hv.w * w23.w;
    #pragma unroll
    for (int off = 16; off >= 1; off >>= 1) {
        d0 += __shfl_xor_sync(0xffffffffu, d0, off);
        d1 += __shfl_xor_sync(0xffffffffu, d1, off);
    }
    if (lane == 0) {
        out[(size_t)row * 2 + 0] = d0 + b2[0];
        out[(size_t)row * 2 + 1] = d1 + b2[1] + (*ecw) * g_signal[row];
        if (out_size >= 3 * bs) {
            int lab = g_idx64 ? y[2 * row] : y[row];
            out[(size_t)2 * bs + row] = (float)lab;
        }
    }
}

// ---------------- launch -----------------------------------------------------
extern "C" void kernel_launch(void* const* d_in, const int* in_sizes, int n_in,
                              void* d_out, int out_size) {
    const float* x         = (const float*)d_in[0];
    const float* edge_attr = (const float*)d_in[1];
    const float* W1        = (const float*)d_in[2];
    const float* b1        = (const float*)d_in[3];
    const float* W2        = (const float*)d_in[4];
    const float* b2        = (const float*)d_in[5];
    const float* V1        = (const float*)d_in[6];
    const float* bv1       = (const float*)d_in[7];
    const float* V2        = (const float*)d_in[8];
    const float* bv2       = (const float*)d_in[9];
    const float* ecw       = (const float*)d_in[10];
    const int*   ei        = (const int*)d_in[11];
    const int*   y         = (const int*)d_in[12];
    const int*   bs_ptr    = (const int*)d_in[13];
    float* out = (float*)d_out;

    int N = in_sizes[0] / 128;
    int E = in_sizes[1] / 128;

    int xg_smem = (AWX + 2 * BWORDS) * 4;   // 96 KB
    int eg_smem = (AWE + 2 * BWORDS) * 4;   // 64 KB
    cudaFuncSetAttribute(xgemm_mma, cudaFuncAttributeMaxDynamicSharedMemorySize, xg_smem);
    cudaFuncSetAttribute(edge_mma,  cudaFuncAttributeMaxDynamicSharedMemorySize, eg_smem);

    prep_kernel<<<(20 * BWORDS + 255) / 256, 256>>>(V1, W1);
    init_compact_kernel<<<(E + 255) / 256, 256>>>(ei, E, N, bs_ptr);

    xgemm_mma<<<(N + 255) / 256, 256, xg_smem>>>(x, b1, N, bs_ptr);

    edge_mma<<<(E + 127) / 128, 256, eg_smem>>>(edge_attr, bv1, V2, bv2, ei, E);

    final_kernel<<<(N * 32 + 255) / 256, 256>>>(W2, b2, ecw, y, bs_ptr, out, out_size, N);
}

// round 17
// speedup vs baseline: 1.2624x; 1.1226x over previous
#include <cuda_runtime.h>
#include <cuda_fp16.h>
#include <cstdint>
#include <math.h>

#define NMAX 100000
#define EMAX 500000
#define AWX 16384     // xgemm A tile: 256 rows x 128 k fp16 (64KB)
#define AWE 8192      // edge  A tile: 128 rows x 128 k fp16 (32KB)
#define BWORDS 4096   // B tile: 128 k x 64 n fp16 (16KB)

// ---------------- scratch ----------------------------------------------------
// g_XAB column layout (per 64-col ct chunk): pos = wn*32 + t4*8 + ni*2 + e
// (fragment order: one uint4 per (thread, mi, half) covers all 4 ni values)
__device__ __align__(16) __half g_XAB[(size_t)NMAX * 768];   // [XA|XB] fp16
__device__ __align__(16) float g_H[(size_t)NMAX * 128];
__device__ __align__(16) unsigned g_Wp[20 * BWORDS];         // permuted fp16 weights
__device__ float g_signal[NMAX];
__device__ int   g_elist[EMAX];
__device__ int   g_ecount;
__device__ int   g_idx64;

// ---------------- helpers -----------------------------------------------------
__device__ __forceinline__ void mma16(float* c, uint4 a, unsigned b0, unsigned b1) {
    asm volatile(
        "mma.sync.aligned.m16n8k16.row.col.f32.f16.f16.f32 "
        "{%0,%1,%2,%3},{%4,%5,%6,%7},{%8,%9},{%0,%1,%2,%3};"
        : "+f"(c[0]), "+f"(c[1]), "+f"(c[2]), "+f"(c[3])
        : "r"(a.x), "r"(a.y), "r"(a.z), "r"(a.w), "r"(b0), "r"(b1));
}
__device__ __forceinline__ void cp16(void* sdst, const void* gsrc) {
    unsigned s = (unsigned)__cvta_generic_to_shared(sdst);
    asm volatile("cp.async.cg.shared.global [%0], [%1], 16;\n" :: "r"(s), "l"(gsrc));
}
__device__ __forceinline__ void cp_commit() { asm volatile("cp.async.commit_group;\n" ::); }
__device__ __forceinline__ void cp_wait1()  { asm volatile("cp.async.wait_group 1;\n" ::: "memory"); }
__device__ __forceinline__ unsigned h2b(float a, float b) {
    __half2 h = __floats2half2_rn(a, b);
    return *reinterpret_cast<unsigned*>(&h);
}

// A permuted word position, 256-row tile (xgemm)
__device__ __forceinline__ int aposx(int r, int k) {
    int wm = r >> 6, mi = (r >> 4) & 3, jbit = (r >> 3) & 1, g = r & 7;
    int kblk = k >> 4, khalf = (k >> 3) & 1, t4 = (k >> 1) & 3;
    return ((wm * 8 + kblk) * 4 + mi) * 128 + (g * 4 + t4) * 4 + khalf * 2 + jbit;
}
// A permuted word position, 128-row tile (edge)
__device__ __forceinline__ int apose(int r, int k) {
    int wm = r >> 5, mi = (r >> 4) & 1, jbit = (r >> 3) & 1, g = r & 7;
    int kblk = k >> 4, khalf = (k >> 3) & 1, t4 = (k >> 1) & 3;
    return ((wm * 8 + kblk) * 2 + mi) * 128 + (g * 4 + t4) * 4 + khalf * 2 + jbit;
}

// ---------------- prep: permute+convert weights to fp16 ----------------------
// tiles: 0..5 V1[0:128], 6..11 V1[128:256], 12..13 W1, 14..19 V1[256:384]
__global__ void prep_kernel(const float* __restrict__ V1, const float* __restrict__ W1) {
    int idx = blockIdx.x * blockDim.x + threadIdx.x;
    if (idx == 0) g_ecount = 0;          // zero before init_compact (stream-ordered)
    if (idx >= 20 * BWORDS) return;
    int tile = idx >> 12;
    int rem  = idx & 4095;
    int kblk = rem >> 9;
    int wn   = (rem >> 8) & 1;
    int h    = (rem >> 7) & 1;
    int lane = (rem >> 2) & 31;
    int nlow = (rem >> 1) & 1;
    int khalf = rem & 1;
    int g = lane >> 2, t4 = lane & 3;
    int ni = 2 * h + nlow;
    int n  = wn * 32 + ni * 8 + g;
    int k  = kblk * 16 + khalf * 8 + t4 * 2;
    float va, vb;
    if (tile < 6) {
        va = V1[(size_t)k * 384 + tile * 64 + n];
        vb = V1[(size_t)(k + 1) * 384 + tile * 64 + n];
    } else if (tile < 12) {
        va = V1[(size_t)(128 + k) * 384 + (tile - 6) * 64 + n];
        vb = V1[(size_t)(129 + k) * 384 + (tile - 6) * 64 + n];
    } else if (tile < 14) {
        va = W1[(size_t)k * 128 + (tile - 12) * 64 + n];
        vb = W1[(size_t)(k + 1) * 128 + (tile - 12) * 64 + n];
    } else {
        va = V1[(size_t)(256 + k) * 384 + (tile - 14) * 64 + n];
        vb = V1[(size_t)(257 + k) * 384 + (tile - 14) * 64 + n];
    }
    g_Wp[idx] = h2b(va, vb);
}

// ---------------- fused init + compact (per-block idx64 sniff) ---------------
__global__ void init_compact_kernel(const int* __restrict__ ei, int E, int N,
                                    const int* __restrict__ bs_ptr) {
    __shared__ int s_cnt, s_base, s_i64;
    int t = threadIdx.x;
    int e = blockIdx.x * blockDim.x + t;
    if (t == 0) {
        s_cnt = 0;
        int allz = 1;
        #pragma unroll
        for (int j = 1; j < 64; j += 2)
            if (ei[j] != 0) { allz = 0; break; }
        s_i64 = allz;
        if (blockIdx.x == 0) g_idx64 = allz;
    }
    __syncthreads();
    if (e < N) g_signal[e] = 0.0f;
    int pos = -1;
    if (e < E) {
        int bs  = *bs_ptr;
        int src = s_i64 ? ei[2 * e] : ei[e];
        if (src < bs) pos = atomicAdd(&s_cnt, 1);
    }
    __syncthreads();
    if (t == 0 && s_cnt > 0) s_base = atomicAdd(&g_ecount, s_cnt);
    __syncthreads();
    if (pos >= 0) g_elist[s_base + pos] = e;
}

// ---------------- fused x-GEMM: persistent A (256 rows), loop ct tiles -------
__global__ __launch_bounds__(256, 2) void xgemm_mma(
    const float* __restrict__ x, const float* __restrict__ b1,
    int N, const int* __restrict__ bs_ptr)
{
    extern __shared__ unsigned usm[];
    unsigned* As  = usm;                 // AWX (persistent)
    unsigned* Bb0 = usm + AWX;           // BWORDS each
    unsigned* Bb1 = Bb0 + BWORDS;

    int bs = *bs_ptr; if (bs > N) bs = N;
    int row0 = blockIdx.x * 256;
    if (row0 >= N) return;
    int ne = min(256, N - row0);
    int t = threadIdx.x;

    int tbase  = (row0 < bs) ? 0 : 6;
    int ntiles = (row0 < bs) ? 14 : 6;

    for (int i = t; i < BWORDS / 4; i += 256)
        cp16(&Bb0[i * 4], &g_Wp[tbase * BWORDS + i * 4]);
    cp_commit();

    for (int i = t; i < 4096; i += 256) {
        int r = i >> 4, c = i & 15;
        int rs = (r < ne) ? (row0 + r) : row0;
        const float4* xp = (const float4*)(x + (size_t)rs * 128 + c * 8);
        float4 v0 = xp[0], v1 = xp[1];
        int k0 = c * 8;
        As[aposx(r, k0)]     = h2b(v0.x, v0.y);
        As[aposx(r, k0 + 2)] = h2b(v0.z, v0.w);
        As[aposx(r, k0 + 4)] = h2b(v1.x, v1.y);
        As[aposx(r, k0 + 6)] = h2b(v1.z, v1.w);
    }

    int lane = t & 31, w = t >> 5;
    int wm = w >> 1, wn = w & 1;         // 4 x 2 warps, warp tile 64x32
    int g = lane >> 2, t4 = lane & 3;

    const uint4* Au = (const uint4*)As;

    #pragma unroll 1
    for (int ti = 0; ti < ntiles; ++ti) {
        int ct = tbase + ti;
        const uint4* Bu = (const uint4*)((ti & 1) ? Bb1 : Bb0);
        unsigned* Bn = (ti & 1) ? Bb0 : Bb1;

        __syncthreads();
        if (ti + 1 < ntiles) {
            for (int i = t; i < BWORDS / 4; i += 256)
                cp16(&Bn[i * 4], &g_Wp[(ct + 1) * BWORDS + i * 4]);
        }
        cp_commit();
        cp_wait1();
        __syncthreads();

        float C[4][4][4] = {};
        #pragma unroll
        for (int kb = 0; kb < 8; kb++) {
            uint4 a0 = Au[((wm * 8 + kb) * 4 + 0) * 32 + lane];
            uint4 a1 = Au[((wm * 8 + kb) * 4 + 1) * 32 + lane];
            uint4 a2 = Au[((wm * 8 + kb) * 4 + 2) * 32 + lane];
            uint4 a3 = Au[((wm * 8 + kb) * 4 + 3) * 32 + lane];
            uint4 b0 = Bu[((kb * 2 + wn) * 2 + 0) * 32 + lane];
            uint4 b1 = Bu[((kb * 2 + wn) * 2 + 1) * 32 + lane];
            mma16(C[0][0], a0, b0.x, b0.y);  mma16(C[0][1], a0, b0.z, b0.w);
            mma16(C[0][2], a0, b1.x, b1.y);  mma16(C[0][3], a0, b1.z, b1.w);
            mma16(C[1][0], a1, b0.x, b0.y);  mma16(C[1][1], a1, b0.z, b0.w);
            mma16(C[1][2], a1, b1.x, b1.y);  mma16(C[1][3], a1, b1.z, b1.w);
            mma16(C[2][0], a2, b0.x, b0.y);  mma16(C[2][1], a2, b0.z, b0.w);
            mma16(C[2][2], a2, b1.x, b1.y);  mma16(C[2][3], a2, b1.z, b1.w);
            mma16(C[3][0], a3, b0.x, b0.y);  mma16(C[3][1], a3, b0.z, b0.w);
            mma16(C[3][2], a3, b1.x, b1.y);  mma16(C[3][3], a3, b1.z, b1.w);
        }

        bool isH = (ct >= 12);
        int mlim = (ct >= 6 && ct < 12) ? ne : min(ne, bs - row0);
        #pragma unroll
        for (int mi = 0; mi < 4; mi++)
            #pragma unroll
            for (int ni = 0; ni < 4; ni++) {
                int ncl = wn * 32 + ni * 8 + 2 * t4;           // true column
                int pcl = wn * 32 + t4 * 8 + ni * 2;           // permuted XAB pos
                #pragma unroll
                for (int half = 0; half < 2; half++) {
                    int r = wm * 64 + mi * 16 + g + half * 8;
                    if (r < mlim) {
                        float v0 = C[mi][ni][half * 2 + 0];
                        float v1 = C[mi][ni][half * 2 + 1];
                        size_t row = row0 + r;
                        if (isH) {
                            int jg = (ct - 12) * 64 + ncl;
                            float2 o;
                            o.x = fmaxf(v0 + b1[jg],     0.f);
                            o.y = fmaxf(v1 + b1[jg + 1], 0.f);
                            *(float2*)(g_H + row * 128 + jg) = o;
                        } else {
                            int jg = ct * 64 + pcl;            // fragment-order slot
                            __half2 o = __floats2half2_rn(v0, v1);
                            *reinterpret_cast<__half2*>(g_XAB + row * 768 + jg) = o;
                        }
                    }
                }
            }
    }
}

// ---------------- edge kernel: 128 edges/block, double-buffered B ------------
__global__ __launch_bounds__(256, 2) void edge_mma(
    const float* __restrict__ edge_attr,
    const float* __restrict__ bv1, const float* __restrict__ V2,
    const float* __restrict__ bv2, const int* __restrict__ ei, int E)
{
    extern __shared__ unsigned usm[];
    unsigned* As  = usm;
    unsigned* Bb0 = usm + AWE;
    unsigned* Bb1 = Bb0 + BWORDS;

    __shared__ int s_src[128], s_dst[128], s_eid[128];
    __shared__ float s_part[128 * 2];

    int cnt = g_ecount;
    int base = blockIdx.x * 128;
    if (base >= cnt) return;
    int ne = min(128, cnt - base);
    int t = threadIdx.x;
    int i64 = g_idx64;

    if (t < 128) {
        int e = 0, ss = 0, dd = 0;
        if (t < ne) {
            e  = g_elist[base + t];
            ss = i64 ? ei[2 * e]       : ei[e];
            dd = i64 ? ei[2 * (E + e)] : ei[E + e];
        }
        s_eid[t] = e; s_src[t] = ss; s_dst[t] = dd;
    }
    s_part[t] = 0.f;
    __syncthreads();

    for (int i = t; i < BWORDS / 4; i += 256)
        cp16(&Bb0[i * 4], &g_Wp[14 * BWORDS + i * 4]);
    cp_commit();

    for (int i = t; i < 2048; i += 256) {
        int r = i >> 4, c = i & 15;
        const float4* xp = (const float4*)(edge_attr + (size_t)s_eid[r] * 128 + c * 8);
        float4 v0 = xp[0], v1 = xp[1];
        int k0 = c * 8;
        As[apose(r, k0)]     = h2b(v0.x, v0.y);
        As[apose(r, k0 + 2)] = h2b(v0.z, v0.w);
        As[apose(r, k0 + 4)] = h2b(v1.x, v1.y);
        As[apose(r, k0 + 6)] = h2b(v1.z, v1.w);
    }

    int lane = t & 31, w = t >> 5;
    int wm = w >> 1, wn = w & 1;      // 4 x 2 warps, warp tile 32x32
    int g = lane >> 2, t4 = lane & 3;
    float psc[2][2] = {};

    const uint4* Au = (const uint4*)As;

    #pragma unroll 1
    for (int ct = 0; ct < 6; ++ct) {
        const uint4* Bu = (const uint4*)((ct & 1) ? Bb1 : Bb0);
        unsigned* Bn = (ct & 1) ? Bb0 : Bb1;

        __syncthreads();
        if (ct < 5) {
            for (int i = t; i < BWORDS / 4; i += 256)
                cp16(&Bn[i * 4], &g_Wp[(15 + ct) * BWORDS + i * 4]);
        }
        cp_commit();

        // fragment-order XAB gather: ONE uint4 per (mi,half,array) covers 4 ni
        uint4 pxa[2][2], pxb[2][2];
        #pragma unroll
        for (int mi = 0; mi < 2; mi++)
            #pragma unroll
            for (int half = 0; half < 2; half++) {
                int r = wm * 32 + mi * 16 + g + half * 8;
                int off = ct * 64 + wn * 32 + t4 * 8;
                pxa[mi][half] = *reinterpret_cast<const uint4*>(
                    g_XAB + (size_t)s_src[r] * 768 + off);
                pxb[mi][half] = *reinterpret_cast<const uint4*>(
                    g_XAB + (size_t)s_dst[r] * 768 + 384 + off);
            }

        cp_wait1();
        __syncthreads();

        float C[2][4][4] = {};
        #pragma unroll
        for (int kb = 0; kb < 8; kb++) {
            uint4 a0 = Au[((wm * 8 + kb) * 2 + 0) * 32 + lane];
            uint4 a1 = Au[((wm * 8 + kb) * 2 + 1) * 32 + lane];
            uint4 b0 = Bu[((kb * 2 + wn) * 2 + 0) * 32 + lane];
            uint4 b1 = Bu[((kb * 2 + wn) * 2 + 1) * 32 + lane];
            mma16(C[0][0], a0, b0.x, b0.y);
            mma16(C[0][1], a0, b0.z, b0.w);
            mma16(C[0][2], a0, b1.x, b1.y);
            mma16(C[0][3], a0, b1.z, b1.w);
            mma16(C[1][0], a1, b0.x, b0.y);
            mma16(C[1][1], a1, b0.z, b0.w);
            mma16(C[1][2], a1, b1.x, b1.y);
            mma16(C[1][3], a1, b1.z, b1.w);
        }

        #pragma unroll
        for (int mi = 0; mi < 2; mi++)
            #pragma unroll
            for (int half = 0; half < 2; half++) {
                int r = wm * 32 + mi * 16 + g + half * 8;
                if (r < ne) {
                    unsigned wa[4] = { pxa[mi][half].x, pxa[mi][half].y,
                                       pxa[mi][half].z, pxa[mi][half].w };
                    unsigned wb[4] = { pxb[mi][half].x, pxb[mi][half].y,
                                       pxb[mi][half].z, pxb[mi][half].w };
                    #pragma unroll
                    for (int ni = 0; ni < 4; ni++) {
                        int ncl = wn * 32 + ni * 8 + 2 * t4;   // true column
                        int jg  = ct * 64 + ncl;
                        float2 bv = *(const float2*)(bv1 + jg);
                        float2 v2 = *(const float2*)(V2 + jg);
                        float2 fa = __half22float2(
                            *reinterpret_cast<__half2*>(&wa[ni]));
                        float2 fb = __half22float2(
                            *reinterpret_cast<__half2*>(&wb[ni]));
                        float h0 = fmaxf(C[mi][ni][half * 2 + 0] + fa.x + fb.x + bv.x, 0.f);
                        float h1 = fmaxf(C[mi][ni][half * 2 + 1] + fa.y + fb.y + bv.y, 0.f);
                        psc[mi][half] += h0 * v2.x + h1 * v2.y;
                    }
                }
            }
    }

    // deterministic per-edge reduction
    #pragma unroll
    for (int mi = 0; mi < 2; mi++)
        #pragma unroll
        for (int half = 0; half < 2; half++) {
            float v = psc[mi][half];
            v += __shfl_xor_sync(0xffffffffu, v, 1);
            v += __shfl_xor_sync(0xffffffffu, v, 2);
            int r = wm * 32 + mi * 16 + g + half * 8;
            if (t4 == 0 && r < ne) s_part[r * 2 + wn] = v;
        }
    __syncthreads();

    if (t < ne) {
        float score = (s_part[t * 2 + 0] + s_part[t * 2 + 1]) + bv2[0];
        float sig = 1.0f / (1.0f + expf(-score));
        atomicMax((int*)&g_signal[s_src[t]], __float_as_int(sig));
    }
}

// ---------------- final: pred = H@W2 + b2 (+signal), labels ------------------
__global__ __launch_bounds__(256) void final_kernel(
    const float* __restrict__ W2, const float* __restrict__ b2,
    const float* __restrict__ ecw, const int* __restrict__ y,
    const int* __restrict__ bs_ptr, float* __restrict__ out,
    int out_size, int N)
{
    int bs = *bs_ptr; if (bs > N) bs = N;
    int row  = (blockIdx.x * blockDim.x + threadIdx.x) >> 5;
    int lane = threadIdx.x & 31;
    if (row >= bs) return;

    float4 hv  = *(const float4*)(g_H + (size_t)row * 128 + lane * 4);
    float4 w01 = *(const float4*)(W2 + lane * 8);
    float4 w23 = *(const float4*)(W2 + lane * 8 + 4);
    float d0 = hv.x * w01.x + hv.y * w01.z + hv.z * w23.x + hv.w * w23.z;
    float d1 = hv.x * w01.y + hv.y * w01.w + hv.z * w23.y + hv.w * w23.w;
    #pragma unroll
    for (int off = 16; off >= 1; off >>= 1) {
        d0 += __shfl_xor_sync(0xffffffffu, d0, off);
        d1 += __shfl_xor_sync(0xffffffffu, d1, off);
    }
    if (lane == 0) {
        out[(size_t)row * 2 + 0] = d0 + b2[0];
        out[(size_t)row * 2 + 1] = d1 + b2[1] + (*ecw) * g_signal[row];
        if (out_size >= 3 * bs) {
            int lab = g_idx64 ? y[2 * row] : y[row];
            out[(size_t)2 * bs + row] = (float)lab;
        }
    }
}

// ---------------- launch -----------------------------------------------------
extern "C" void kernel_launch(void* const* d_in, const int* in_sizes, int n_in,
                              void* d_out, int out_size) {
    const float* x         = (const float*)d_in[0];
    const float* edge_attr = (const float*)d_in[1];
    const float* W1        = (const float*)d_in[2];
    const float* b1        = (const float*)d_in[3];
    const float* W2        = (const float*)d_in[4];
    const float* b2        = (const float*)d_in[5];
    const float* V1        = (const float*)d_in[6];
    const float* bv1       = (const float*)d_in[7];
    const float* V2        = (const float*)d_in[8];
    const float* bv2       = (const float*)d_in[9];
    const float* ecw       = (const float*)d_in[10];
    const int*   ei        = (const int*)d_in[11];
    const int*   y         = (const int*)d_in[12];
    const int*   bs_ptr    = (const int*)d_in[13];
    float* out = (float*)d_out;

    int N = in_sizes[0] / 128;
    int E = in_sizes[1] / 128;

    int xg_smem = (AWX + 2 * BWORDS) * 4;   // 96 KB
    int eg_smem = (AWE + 2 * BWORDS) * 4;   // 64 KB
    cudaFuncSetAttribute(xgemm_mma, cudaFuncAttributeMaxDynamicSharedMemorySize, xg_smem);
    cudaFuncSetAttribute(edge_mma,  cudaFuncAttributeMaxDynamicSharedMemorySize, eg_smem);

    prep_kernel<<<(20 * BWORDS + 255) / 256, 256>>>(V1, W1);
    init_compact_kernel<<<(E + 255) / 256, 256>>>(ei, E, N, bs_ptr);

    xgemm_mma<<<(N + 255) / 256, 256, xg_smem>>>(x, b1, N, bs_ptr);

    edge_mma<<<(E + 127) / 128, 256, eg_smem>>>(edge_attr, bv1, V2, bv2, ei, E);

    final_kernel<<<(N * 32 + 255) / 256, 256>>>(W2, b2, ecw, y, bs_ptr, out, out_size, N);
}